// round 17
// baseline (speedup 1.0000x reference)
#include <cuda_runtime.h>
#include <cuda_fp16.h>
#include <cstdint>

// ---------------------------------------------------------------------------
// int4 group-quantized GEMM via mma.sync (HMMA), fp32 I/O.
// y[512, 11008] = x[512, 4096] @ dequant(W)[11008, 4096]^T
// w = scale[n, k/128] * (q - 8); each int32 holds one byte (2 nibbles).
//
// R17 = R16 + 4 A-buffers. R16's race: issue_a(st+2) (top of iter, after
// prev barrier) overwrote A[(st+2)%3] == A[(st-1)%3] still being read by
// laggard warps' compute(st-1). With 4 bufs the overwritten buffer's last
// reader is compute(st-2), separated from the write by iter st-1's barrier.
// CTA 128x256, 8 warps 64x64, 1 CTA/SM, split-K=4, in-loop dequant.
// ---------------------------------------------------------------------------

#define M_TOTAL 512
#define N_TOTAL 11008
#define K_TOTAL 4096
#define KW_INT  2048
#define NGROUPS 32

#define MT 128
#define NT 256
#define KT 64
#define NSPLIT 4
#define KSPLIT (K_TOTAL / NSPLIT)        // 1024
#define NSTAGES (KSPLIT / KT)            // 16 per CTA
#define THREADS 256

#define SWZ128(bo) ((bo) ^ (((bo) >> 3) & 0x70))

#define A_BYTES 16384                    // 128 rows x 128B
#define B_BYTES 32768                    // 256 rows x 128B
#define SMEM_A_OFF(b)    ((b) * A_BYTES)                  // 4 bufs: 0..64K
#define SMEM_BF_OFF(b)   (4 * A_BYTES + (b) * B_BYTES)    // 2 bufs: 64..128K
#define SMEM_BRAW_OFF(b) (4 * A_BYTES + 2 * B_BYTES + (b) * B_BYTES) // 3 bufs
#define SMEM_TOTAL (4 * A_BYTES + 5 * B_BYTES)            // 224 KB

__device__ __align__(16) __half g_xh[M_TOTAL * K_TOTAL];               // 4 MB
__device__ __align__(16) float  g_part[(size_t)NSPLIT * M_TOTAL * N_TOTAL]; // 90 MB

// ---------------- PTX helpers ----------------
__device__ __forceinline__ uint32_t smem_u32(const void* p) {
    uint32_t a;
    asm("{ .reg .u64 t; cvta.to.shared.u64 t, %1; cvt.u32.u64 %0, t; }"
        : "=r"(a) : "l"(p));
    return a;
}

__device__ __forceinline__ void cp_async16(uint32_t saddr, const void* g) {
    asm volatile("cp.async.cg.shared.global [%0], [%1], 16;"
                 :: "r"(saddr), "l"(g) : "memory");
}
#define CP_COMMIT() asm volatile("cp.async.commit_group;" ::: "memory")
#define CP_WAIT1()  asm volatile("cp.async.wait_group 1;" ::: "memory")

__device__ __forceinline__ void ldsm4(uint32_t* r, uint32_t a) {
    asm volatile("ldmatrix.sync.aligned.m8n8.x4.shared.b16 {%0,%1,%2,%3}, [%4];"
                 : "=r"(r[0]), "=r"(r[1]), "=r"(r[2]), "=r"(r[3]) : "r"(a));
}

__device__ __forceinline__ void mma16816(float* c, const uint32_t* a,
                                         const uint32_t* b) {
    asm volatile(
        "mma.sync.aligned.m16n8k16.row.col.f32.f16.f16.f32 "
        "{%0,%1,%2,%3}, {%4,%5,%6,%7}, {%8,%9}, {%0,%1,%2,%3};"
        : "+f"(c[0]), "+f"(c[1]), "+f"(c[2]), "+f"(c[3])
        : "r"(a[0]), "r"(a[1]), "r"(a[2]), "r"(a[3]), "r"(b[0]), "r"(b[1]));
}

// dequant one packed byte -> half2 {lo-8, hi-8} * s2  (exact via 0x6400 bias)
__device__ __forceinline__ __half2 dq(int b, __half2 s2, __half2 c1032) {
    uint32_t u = (uint32_t)(b & 0xF) | (((uint32_t)b << 12) & 0x000F0000u)
               | 0x64006400u;
    __half2 h = __hsub2(*reinterpret_cast<__half2*>(&u), c1032);
    return __hmul2(h, s2);
}

// ---------------- pre-kernel: x fp32 -> fp16 ----------------
#define XV (M_TOTAL * K_TOTAL / 4)

__global__ void __launch_bounds__(256)
cvt_x(const float* __restrict__ x) {
    int i = blockIdx.x * blockDim.x + threadIdx.x;
    if (i < XV) {
        float4 f = reinterpret_cast<const float4*>(x)[i];
        union { __half2 h[2]; uint2 u; } p;
        p.h[0] = __floats2half2_rn(f.x, f.y);
        p.h[1] = __floats2half2_rn(f.z, f.w);
        reinterpret_cast<uint2*>(g_xh)[i] = p.u;
    }
}

// ---------------- main GEMM kernel ----------------
__global__ void __launch_bounds__(THREADS, 1)
gemm_hmma(const int* __restrict__ wp, const float* __restrict__ sc) {
    extern __shared__ __align__(1024) char smem[];
    const uint32_t sbase = smem_u32(smem);

    const int tid = threadIdx.x;
    const int wid = tid >> 5;
    const int lid = tid & 31;
    const int wm = (wid >> 2) * 64;   // 2x4 warp grid, 64x64 warp tile
    const int wn = (wid & 3) * 64;

    const int m0 = blockIdx.x * MT;   // fast dim: M-siblings share weights in L2
    const int n0 = blockIdx.y * NT;
    const int kz = blockIdx.z * KSPLIT;

    const int jA = lid >> 3, rA = lid & 7;
    const int a_row_l = (jA & 1) * 8 + rA;
    const int a_kb_l  = (jA >> 1) * 16;
    const int b_row_l = (jA >> 1) * 8 + rA;
    const int b_kb_l  = (jA & 1) * 16;

    const __half2 c1032 = __half2half2(__ushort_as_half((unsigned short)0x6408));

    float acc[4][8][4];
    #pragma unroll
    for (int i = 0; i < 4; ++i)
        #pragma unroll
        for (int j = 0; j < 8; ++j)
            #pragma unroll
            for (int k = 0; k < 4; ++k) acc[i][j][k] = 0.f;

    auto issue_a = [&](int k0, int buf) {
        const uint32_t abase = sbase + SMEM_A_OFF(buf);
        #pragma unroll
        for (int it = 0; it < 4; ++it) {
            int t = tid + it * THREADS;       // 0..1023
            int row = t >> 3, ch = t & 7;
            const void* src = g_xh + (size_t)(m0 + row) * K_TOTAL + k0 + ch * 8;
            uint32_t bo = row * 128 + ch * 16;
            cp_async16(abase + SWZ128(bo), src);
        }
    };

    // raw packed B: 256 rows x 32 int32 (=128B). Coalesced loads, XOR swizzle
    // (chunk c of row r at r*128 + (c ^ (r&7))*16) for conflict-free LDS.128.
    auto issue_braw = [&](int k0, int buf) {
        const uint32_t rbase = sbase + SMEM_BRAW_OFF(buf);
        const int c = tid & 7;
        #pragma unroll
        for (int it = 0; it < 8; ++it) {
            int row = (tid >> 3) + it * 32;   // 0..255
            const int* src = wp + (size_t)(n0 + row) * KW_INT + (k0 >> 1) + c * 4;
            cp_async16(rbase + (uint32_t)(row * 128 + ((c ^ (row & 7)) << 4)),
                       src);
        }
    };

    // thread tid dequants weight row (n0+tid): 8 x (LDS.128 -> 4 dq -> STS.128)
    auto dequant = [&](int rbuf, int fbuf, float s) {
        const __half2 s2 = __half2half2(__float2half_rn(s));
        const uint32_t rb = SMEM_BRAW_OFF(rbuf) + (uint32_t)tid * 128;
        const uint32_t fb = SMEM_BF_OFF(fbuf);
        #pragma unroll
        for (int j = 0; j < 8; ++j) {
            int4 pv = *reinterpret_cast<const int4*>(
                smem + rb + ((j ^ (tid & 7)) << 4));
            union { __half2 h[4]; uint4 u; } pk;
            pk.h[0] = dq(pv.x, s2, c1032);
            pk.h[1] = dq(pv.y, s2, c1032);
            pk.h[2] = dq(pv.z, s2, c1032);
            pk.h[3] = dq(pv.w, s2, c1032);
            *reinterpret_cast<uint4*>(
                smem + fb + SWZ128((uint32_t)tid * 128 + j * 16)) = pk.u;
        }
    };

    // scale row pointer biased by this CTA's K-offset group
    const float* srow = sc + (size_t)(n0 + tid) * NGROUPS + (kz >> 7);

    // ---- prologue: stages 0,1 in flight; dequant stage 0 ----
    issue_a(kz, 0);      issue_braw(kz, 0);      CP_COMMIT();   // g0
    issue_a(kz + KT, 1); issue_braw(kz + KT, 1); CP_COMMIT();   // g1
    CP_WAIT1();                       // this thread's stage-0 data landed
    __syncthreads();                  // ALL threads' stage-0 data visible
    dequant(0, 0, srow[0]);           // writes BF0 (read after next barrier)

    // ---- main loop ----
    int a_c = 0, a_p = 2;             // A: st%4, (st+2)%4
    int r_d = 1, r_p = 2;             // BRAW: (st+1)%3, (st+2)%3
    #pragma unroll 1
    for (int st = 0; st < NSTAGES; ++st) {
        if (st + 2 < NSTAGES) {
            issue_a(kz + (st + 2) * KT, a_p);
            issue_braw(kz + (st + 2) * KT, r_p);
        }
        CP_COMMIT();
        CP_WAIT1();                   // stage st+1 (this thread) landed
        __syncthreads();              // all threads' st+1 data visible;
                                      // publishes BF[st&1]; fences compute(st-1)

        if (st + 1 < NSTAGES)
            dequant(r_d, (st + 1) & 1, srow[(st + 1) >> 1]);

        // ---- compute stage st (ks-pipelined fragments) ----
        const uint32_t abase = sbase + SMEM_A_OFF(a_c);
        const uint32_t bbase = sbase + SMEM_BF_OFF(st & 1);
        uint32_t af[2][4][4];
        uint32_t bf[2][4][4];
        #pragma unroll
        for (int mt = 0; mt < 4; ++mt)
            ldsm4(af[0][mt], abase + SWZ128(
                (uint32_t)(wm + mt * 16 + a_row_l) * 128 + a_kb_l));
        #pragma unroll
        for (int np = 0; np < 4; ++np)
            ldsm4(bf[0][np], bbase + SWZ128(
                (uint32_t)(wn + np * 16 + b_row_l) * 128 + b_kb_l));

        #pragma unroll
        for (int ks = 0; ks < 4; ++ks) {
            const int cur = ks & 1, nxt = cur ^ 1;
            if (ks < 3) {
                const int kb = (ks + 1) * 32;
                #pragma unroll
                for (int mt = 0; mt < 4; ++mt)
                    ldsm4(af[nxt][mt], abase + SWZ128(
                        (uint32_t)(wm + mt * 16 + a_row_l) * 128 + kb + a_kb_l));
                #pragma unroll
                for (int np = 0; np < 4; ++np)
                    ldsm4(bf[nxt][np], bbase + SWZ128(
                        (uint32_t)(wn + np * 16 + b_row_l) * 128 + kb + b_kb_l));
            }
            #pragma unroll
            for (int mt = 0; mt < 4; ++mt)
                #pragma unroll
                for (int nt = 0; nt < 8; ++nt)
                    mma16816(acc[mt][nt], af[cur][mt],
                             &bf[cur][nt >> 1][(nt & 1) * 2]);
        }

        a_c = (a_c + 1) & 3;
        a_p = (a_p + 1) & 3;
        r_d = (r_d == 2) ? 0 : r_d + 1;
        r_p = (r_p == 2) ? 0 : r_p + 1;
    }

    // ---- epilogue: raw fp32 partials (deterministic) ----
    float* part = g_part + (size_t)blockIdx.z * M_TOTAL * N_TOTAL;
    const int crow = lid >> 2;
    const int ccol = (lid & 3) * 2;
    #pragma unroll
    for (int mt = 0; mt < 4; ++mt) {
        #pragma unroll
        for (int nt = 0; nt < 8; ++nt) {
            const int r = m0 + wm + mt * 16 + crow;
            const int c = n0 + wn + nt * 8 + ccol;
            *reinterpret_cast<float2*>(part + (size_t)r * N_TOTAL + c) =
                make_float2(acc[mt][nt][0], acc[mt][nt][1]);
            *reinterpret_cast<float2*>(part + (size_t)(r + 8) * N_TOTAL + c) =
                make_float2(acc[mt][nt][2], acc[mt][nt][3]);
        }
    }
}

// ---------------- reduce: sum 4 partials, round through fp16 ----------------
#define YV ((size_t)M_TOTAL * N_TOTAL / 4)

__global__ void __launch_bounds__(256)
reduce_y(float* __restrict__ y) {
    size_t i = (size_t)blockIdx.x * 256 + threadIdx.x;
    if (i >= YV) return;
    const size_t stride = (size_t)M_TOTAL * N_TOTAL / 4;
    const float4* p = reinterpret_cast<const float4*>(g_part);
    float4 a0 = p[i];
    float4 a1 = p[i + stride];
    float4 a2 = p[i + 2 * stride];
    float4 a3 = p[i + 3 * stride];
    float4 o;
    o.x = __half2float(__float2half_rn((a0.x + a1.x) + (a2.x + a3.x)));
    o.y = __half2float(__float2half_rn((a0.y + a1.y) + (a2.y + a3.y)));
    o.z = __half2float(__float2half_rn((a0.z + a1.z) + (a2.z + a3.z)));
    o.w = __half2float(__float2half_rn((a0.w + a1.w) + (a2.w + a3.w)));
    reinterpret_cast<float4*>(y)[i] = o;
}

extern "C" void kernel_launch(void* const* d_in, const int* in_sizes, int n_in,
                              void* d_out, int out_size) {
    const float* x      = (const float*)d_in[0];
    const int*   wp     = (const int*)d_in[1];
    const float* scales = (const float*)d_in[2];
    float*       y      = (float*)d_out;

    cvt_x<<<(XV + 255) / 256, 256>>>(x);

    cudaFuncSetAttribute(gemm_hmma,
                         cudaFuncAttributeMaxDynamicSharedMemorySize,
                         SMEM_TOTAL);
    dim3 grid(M_TOTAL / MT, N_TOTAL / NT, NSPLIT);   // (4, 43, 4)
    gemm_hmma<<<grid, THREADS, SMEM_TOTAL>>>(wp, scales);

    reduce_y<<<(unsigned)((YV + 255) / 256), 256>>>(y);
}